// round 6
// baseline (speedup 1.0000x reference)
#include <cuda_runtime.h>
#include <cuda_fp16.h>

#define N_NODES 50000
#define N_EDGES 1600000
#define NCLS    48
#define NH2     24            // active half2 per row
#define ROWP    32            // padded half2 per row (128B rows)
#define NSTEP   10
#define SCAN_B  1024
#define CHUNK   49            // ceil(50000/1024)
#define PERS_BLOCKS 1216      // 152 SMs * 8 blocks: one full wave on GB300

// ---------------- device scratch (static, no runtime allocation) -------------
__device__ float   g_deg[N_NODES];
__device__ int     g_cnt[N_NODES];
__device__ int     g_off[N_NODES + 1];
__device__ int     g_cur[N_NODES];
__device__ short   g_cls[N_EDGES];                   // target[src] per original edge
__device__ __align__(16) int2 g_edge[N_EDGES];       // (src, weight packed half2(w,w))
__device__ __align__(16) int  g_e1[N_EDGES];         // (cls<<16 | w_half_bits), CSR order
__device__ __half2 g_hh[2][(size_t)N_NODES * ROWP];  // fp16 feature buffers, 128B rows

static __device__ __forceinline__ __half2 bits2h2(int b) {
    __half2 h; *reinterpret_cast<int*>(&h) = b; return h;
}

// ---------------- preprocessing ------------------------------------------------
__global__ void deg_kernel(const int* __restrict__ row, const int* __restrict__ col,
                           const float* __restrict__ attr, const int* __restrict__ target) {
    int e = blockIdx.x * blockDim.x + threadIdx.x;
    if (e < N_EDGES) {
        int r = row[e];
        atomicAdd(&g_deg[r], attr[e]);
        atomicAdd(&g_cnt[col[e]], 1);
        g_cls[e] = (short)target[r];
    }
}

// single-block exclusive scan of g_cnt -> g_off / g_cur (3-phase)
__global__ void scan_kernel() {
    __shared__ int sh[SCAN_B];
    int tid = threadIdx.x;
    int base = tid * CHUNK;

    int sum = 0;
    #pragma unroll 4
    for (int k = 0; k < CHUNK; k++) {
        int i = base + k;
        if (i < N_NODES) sum += g_cnt[i];
    }
    sh[tid] = sum;
    __syncthreads();
    for (int d = 1; d < SCAN_B; d <<= 1) {
        int t = (tid >= d) ? sh[tid - d] : 0;
        __syncthreads();
        sh[tid] += t;
        __syncthreads();
    }
    int run = sh[tid] - sum;
    #pragma unroll 4
    for (int k = 0; k < CHUNK; k++) {
        int i = base + k;
        if (i < N_NODES) {
            g_off[i] = run;
            g_cur[i] = run;
            run += g_cnt[i];
        }
    }
    if (tid == 0) g_off[N_NODES] = N_EDGES;
}

__global__ void fill_kernel(const int* __restrict__ row, const int* __restrict__ col,
                            const float* __restrict__ attr) {
    int e = blockIdx.x * blockDim.x + threadIdx.x;
    if (e < N_EDGES) {
        int r = row[e];
        int c = col[e];
        float w = attr[e] / fmaxf(g_deg[r], 1e-12f);
        __half wh = __float2half_rn(w);
        unsigned short wb = __half_as_ushort(wh);
        __half2 wh2 = __halves2half2(wh, wh);
        int p = atomicAdd(&g_cur[c], 1);
        g_edge[p] = make_int2(r, *reinterpret_cast<int*>(&wh2));
        g_e1[p]   = ((int)g_cls[e] << 16) | (int)wb;
    }
}

// ---------------- step 0: one-hot propagation via per-warp smem histogram ------
// edges distributed across lanes (coalesced reads), atomicAdd into 48-bin hist
__global__ void __launch_bounds__(256)
step1_kernel(const float* __restrict__ Wm, float* __restrict__ out) {
    __shared__ float hist[8][NCLS];
    int wip  = threadIdx.x >> 5;
    int lane = threadIdx.x & 31;
    float* h = hist[wip];

    int gw = (blockIdx.x * blockDim.x + threadIdx.x) >> 5;
    int nw = (gridDim.x * blockDim.x) >> 5;

    __half2* __restrict__ hout = g_hh[1];

    for (int n = gw; n < N_NODES; n += nw) {
        if (lane < NH2) { h[lane] = 0.f; h[lane + NH2] = 0.f; }
        __syncwarp();

        int beg = g_off[n];
        int end = g_off[n + 1];
        for (int j = beg + lane; j < end; j += 32) {
            int v = g_e1[j];
            float w = __half2float(__ushort_as_half((unsigned short)(v & 0xffff)));
            atomicAdd(&h[v >> 16], w);
        }
        __syncwarp();

        if (lane < NH2) {
            float accx = h[2 * lane];
            float accy = h[2 * lane + 1];
            hout[(size_t)n * ROWP + lane] = __floats2half2_rn(accx, accy);
            float2 o;
            o.x = accx * Wm[(2 * lane) * NSTEP];       // s = 0
            o.y = accy * Wm[(2 * lane + 1) * NSTEP];
            float2* op = (float2*)(out + (size_t)n * NCLS) + lane;
            *op = o;                                    // overwrite poisoned out
        }
        __syncwarp();   // reads done before next iteration re-zeros
    }
}

// ---------------- steps 1..9: persistent, one warp per node (grid-stride) -----
__global__ void __launch_bounds__(256)
gather_kernel(const float* __restrict__ Wm, float* __restrict__ out, int s) {
    int lane = threadIdx.x & 31;
    int gw = (blockIdx.x * blockDim.x + threadIdx.x) >> 5;
    int nw = (gridDim.x * blockDim.x) >> 5;

    const __half2* __restrict__ hin  = g_hh[s & 1] + lane;   // lane-offset base
    __half2*       __restrict__ hout = g_hh[(s & 1) ^ 1];
    bool act = (lane < NH2);

    for (int n = gw; n < N_NODES; n += nw) {
        int beg = g_off[n];
        int end = g_off[n + 1];

        float accx = 0.f, accy = 0.f;
        __half2 hacc = __floats2half2_rn(0.f, 0.f);

        int j = beg;
        if ((j & 1) && j < end) {               // align int4 metadata loads
            int2 e = g_edge[j];
            if (act) {
                __half2 x = hin[(unsigned)e.x << 5];
                hacc = __hfma2(bits2h2(e.y), x, hacc);
            }
            j++;
        }

        for (; j + 8 <= end; j += 8) {
            int4 m0 = *reinterpret_cast<const int4*>(g_edge + j);
            int4 m1 = *reinterpret_cast<const int4*>(g_edge + j + 2);
            int4 m2 = *reinterpret_cast<const int4*>(g_edge + j + 4);
            int4 m3 = *reinterpret_cast<const int4*>(g_edge + j + 6);
            if (act) {
                __half2 x0 = hin[(unsigned)m0.x << 5];
                __half2 x1 = hin[(unsigned)m0.z << 5];
                __half2 x2 = hin[(unsigned)m1.x << 5];
                __half2 x3 = hin[(unsigned)m1.z << 5];
                __half2 x4 = hin[(unsigned)m2.x << 5];
                __half2 x5 = hin[(unsigned)m2.z << 5];
                __half2 x6 = hin[(unsigned)m3.x << 5];
                __half2 x7 = hin[(unsigned)m3.z << 5];
                __half2 p0 = __hmul2(bits2h2(m0.y), x0);
                __half2 p1 = __hmul2(bits2h2(m0.w), x1);
                p0 = __hfma2(bits2h2(m1.y), x2, p0);
                p1 = __hfma2(bits2h2(m1.w), x3, p1);
                p0 = __hfma2(bits2h2(m2.y), x4, p0);
                p1 = __hfma2(bits2h2(m2.w), x5, p1);
                p0 = __hfma2(bits2h2(m3.y), x6, p0);
                p1 = __hfma2(bits2h2(m3.w), x7, p1);
                float2 f = __half22float2(__hadd2(p0, p1));
                accx += f.x;
                accy += f.y;
            }
        }
        for (; j < end; j++) {
            int2 e = g_edge[j];
            if (act) {
                __half2 x = hin[(unsigned)e.x << 5];
                hacc = __hfma2(bits2h2(e.y), x, hacc);
            }
        }

        if (act) {
            float2 fr = __half22float2(hacc);
            accx += fr.x;
            accy += fr.y;

            hout[(size_t)n * ROWP + lane] = __floats2half2_rn(accx, accy);

            float2 o;
            o.x = accx * Wm[(2 * lane) * NSTEP + s];
            o.y = accy * Wm[(2 * lane + 1) * NSTEP + s];
            float2* op = (float2*)(out + (size_t)n * NCLS) + lane;
            float2 p = *op; o.x += p.x; o.y += p.y;
            *op = o;
        }
    }
}

// ---------------- launch ------------------------------------------------------
extern "C" void kernel_launch(void* const* d_in, const int* in_sizes, int n_in,
                              void* d_out, int out_size) {
    const int*   ei     = (const int*)d_in[0];     // [2, E]
    const int*   row    = ei;
    const int*   col    = ei + N_EDGES;
    const float* attr   = (const float*)d_in[1];   // [E]
    const int*   target = (const int*)d_in[2];     // [N]
    const float* Wm     = (const float*)d_in[3];   // [C, S]
    float*       out    = (float*)d_out;           // [N, C]

    void* p_deg = nullptr; void* p_cnt = nullptr;
    cudaGetSymbolAddress(&p_deg, g_deg);
    cudaGetSymbolAddress(&p_cnt, g_cnt);
    cudaMemsetAsync(p_deg, 0, N_NODES * sizeof(float));
    cudaMemsetAsync(p_cnt, 0, N_NODES * sizeof(int));

    const int TB = 256;
    int nblk_edges = (N_EDGES + TB - 1) / TB;

    deg_kernel<<<nblk_edges, TB>>>(row, col, attr, target);   // launch 1
    scan_kernel<<<1, SCAN_B>>>();                             // launch 2
    fill_kernel<<<nblk_edges, TB>>>(row, col, attr);          // launch 3

    step1_kernel<<<PERS_BLOCKS, TB>>>(Wm, out);               // launch 4 (s=0)
    for (int s = 1; s < NSTEP; s++) {
        gather_kernel<<<PERS_BLOCKS, TB>>>(Wm, out, s);       // launches 5..13
    }
}

// round 8
// speedup vs baseline: 1.4816x; 1.4816x over previous
#include <cuda_runtime.h>
#include <cuda_fp16.h>

#define N_NODES 50000
#define N_EDGES 1600000
#define NCLS    48
#define NH2     24            // active half2 per row
#define ROWP    32            // padded half2 per row (128B rows)
#define NSTEP   10
#define SCAN_B  1024
#define CHUNK   49            // ceil(50000/1024)
#define PERS_BLOCKS 1216      // persistent grid for step1 only

// ---------------- device scratch (static, no runtime allocation) -------------
__device__ float   g_deg[N_NODES];
__device__ int     g_cnt[N_NODES];
__device__ int     g_off[N_NODES + 1];
__device__ int     g_cur[N_NODES];
__device__ short   g_cls[N_EDGES];                   // target[src] per original edge
__device__ __align__(16) unsigned g_epk[N_EDGES];    // (src<<16 | w_half_bits), CSR order
__device__ __align__(16) unsigned g_e1[N_EDGES];     // (cls<<16 | w_half_bits), CSR order
__device__ __half2 g_hh[2][(size_t)N_NODES * ROWP];  // fp16 feature buffers, 128B rows

static __device__ __forceinline__ __half2 wrep(unsigned v) {
    // replicate low 16 bits into both halves of a half2 (one PRMT)
    unsigned r = __byte_perm(v, v, 0x1010);
    __half2 h; *reinterpret_cast<unsigned*>(&h) = r; return h;
}
static __device__ __forceinline__ unsigned srcidx(unsigned v) { return v >> 16; }

// ---------------- preprocessing ------------------------------------------------
__global__ void deg_kernel(const int* __restrict__ row, const int* __restrict__ col,
                           const float* __restrict__ attr, const int* __restrict__ target) {
    int e = blockIdx.x * blockDim.x + threadIdx.x;
    if (e < N_EDGES) {
        int r = row[e];
        atomicAdd(&g_deg[r], attr[e]);
        atomicAdd(&g_cnt[col[e]], 1);
        g_cls[e] = (short)target[r];
    }
}

// single-block exclusive scan of g_cnt -> g_off / g_cur (3-phase)
__global__ void scan_kernel() {
    __shared__ int sh[SCAN_B];
    int tid = threadIdx.x;
    int base = tid * CHUNK;

    int sum = 0;
    #pragma unroll 4
    for (int k = 0; k < CHUNK; k++) {
        int i = base + k;
        if (i < N_NODES) sum += g_cnt[i];
    }
    sh[tid] = sum;
    __syncthreads();
    for (int d = 1; d < SCAN_B; d <<= 1) {
        int t = (tid >= d) ? sh[tid - d] : 0;
        __syncthreads();
        sh[tid] += t;
        __syncthreads();
    }
    int run = sh[tid] - sum;
    #pragma unroll 4
    for (int k = 0; k < CHUNK; k++) {
        int i = base + k;
        if (i < N_NODES) {
            g_off[i] = run;
            g_cur[i] = run;
            run += g_cnt[i];
        }
    }
    if (tid == 0) g_off[N_NODES] = N_EDGES;
}

__global__ void fill_kernel(const int* __restrict__ row, const int* __restrict__ col,
                            const float* __restrict__ attr) {
    int e = blockIdx.x * blockDim.x + threadIdx.x;
    if (e < N_EDGES) {
        int r = row[e];
        int c = col[e];
        float w = attr[e] / fmaxf(g_deg[r], 1e-12f);
        unsigned wb = (unsigned)__half_as_ushort(__float2half_rn(w));
        int p = atomicAdd(&g_cur[c], 1);
        g_epk[p] = ((unsigned)r << 16) | wb;
        g_e1[p]  = ((unsigned)g_cls[e] << 16) | wb;
    }
}

// ---------------- step 0: one-hot propagation via per-warp smem histogram ------
__global__ void __launch_bounds__(256)
step1_kernel(const float* __restrict__ Wm, float* __restrict__ out) {
    __shared__ float hist[8][NCLS];
    int wip  = threadIdx.x >> 5;
    int lane = threadIdx.x & 31;
    float* h = hist[wip];

    int gw = (blockIdx.x * blockDim.x + threadIdx.x) >> 5;
    int nw = (gridDim.x * blockDim.x) >> 5;

    __half2* __restrict__ hout = g_hh[1];

    for (int n = gw; n < N_NODES; n += nw) {
        if (lane < NH2) { h[lane] = 0.f; h[lane + NH2] = 0.f; }
        __syncwarp();

        int beg = g_off[n];
        int end = g_off[n + 1];
        for (int j = beg + lane; j < end; j += 32) {
            unsigned v = g_e1[j];
            float w = __half2float(__ushort_as_half((unsigned short)(v & 0xffffu)));
            atomicAdd(&h[v >> 16], w);
        }
        __syncwarp();

        if (lane < NH2) {
            float accx = h[2 * lane];
            float accy = h[2 * lane + 1];
            hout[(size_t)n * ROWP + lane] = __floats2half2_rn(accx, accy);
            float2 o;
            o.x = accx * Wm[(2 * lane) * NSTEP];       // s = 0
            o.y = accy * Wm[(2 * lane + 1) * NSTEP];
            float2* op = (float2*)(out + (size_t)n * NCLS) + lane;
            *op = o;                                    // overwrite poisoned out
        }
        __syncwarp();
    }
}

// ---------------- steps 1..9: one warp per node, packed 4B edge metadata ------
__global__ void __launch_bounds__(256)
gather_kernel(const float* __restrict__ Wm, float* __restrict__ out, int s) {
    int gwarp = (blockIdx.x * blockDim.x + threadIdx.x) >> 5;
    int lane  = threadIdx.x & 31;
    if (gwarp >= N_NODES) return;

    const __half2* __restrict__ hin  = g_hh[s & 1] + lane;   // lane-offset base
    __half2*       __restrict__ hout = g_hh[(s & 1) ^ 1];

    int beg = g_off[gwarp];
    int end = g_off[gwarp + 1];
    bool act = (lane < NH2);

    float accx = 0.f, accy = 0.f;
    __half2 hacc = __floats2half2_rn(0.f, 0.f);

    int j = beg;
    // peel to 16B alignment of the packed metadata
    for (; j < end && (j & 3); j++) {
        unsigned v = g_epk[j];
        if (act) {
            __half2 x = hin[srcidx(v) << 5];
            hacc = __hfma2(wrep(v), x, hacc);
        }
    }

    for (; j + 8 <= end; j += 8) {
        uint4 m0 = __ldcs(reinterpret_cast<const uint4*>(g_epk + j));
        uint4 m1 = __ldcs(reinterpret_cast<const uint4*>(g_epk + j + 4));
        if (act) {
            __half2 x0 = hin[srcidx(m0.x) << 5];
            __half2 x1 = hin[srcidx(m0.y) << 5];
            __half2 x2 = hin[srcidx(m0.z) << 5];
            __half2 x3 = hin[srcidx(m0.w) << 5];
            __half2 x4 = hin[srcidx(m1.x) << 5];
            __half2 x5 = hin[srcidx(m1.y) << 5];
            __half2 x6 = hin[srcidx(m1.z) << 5];
            __half2 x7 = hin[srcidx(m1.w) << 5];
            __half2 p0 = __hmul2(wrep(m0.x), x0);
            __half2 p1 = __hmul2(wrep(m0.y), x1);
            p0 = __hfma2(wrep(m0.z), x2, p0);
            p1 = __hfma2(wrep(m0.w), x3, p1);
            p0 = __hfma2(wrep(m1.x), x4, p0);
            p1 = __hfma2(wrep(m1.y), x5, p1);
            p0 = __hfma2(wrep(m1.z), x6, p0);
            p1 = __hfma2(wrep(m1.w), x7, p1);
            float2 f = __half22float2(__hadd2(p0, p1));
            accx += f.x;
            accy += f.y;
        }
    }
    for (; j < end; j++) {
        unsigned v = g_epk[j];
        if (act) {
            __half2 x = hin[srcidx(v) << 5];
            hacc = __hfma2(wrep(v), x, hacc);
        }
    }

    if (act) {
        float2 fr = __half22float2(hacc);
        accx += fr.x;
        accy += fr.y;

        hout[(size_t)gwarp * ROWP + lane] = __floats2half2_rn(accx, accy);

        float2 o;
        o.x = accx * Wm[(2 * lane) * NSTEP + s];
        o.y = accy * Wm[(2 * lane + 1) * NSTEP + s];
        float2* op = (float2*)(out + (size_t)gwarp * NCLS) + lane;
        float2 p = *op; o.x += p.x; o.y += p.y;
        *op = o;
    }
}

// ---------------- launch ------------------------------------------------------
extern "C" void kernel_launch(void* const* d_in, const int* in_sizes, int n_in,
                              void* d_out, int out_size) {
    const int*   ei     = (const int*)d_in[0];     // [2, E]
    const int*   row    = ei;
    const int*   col    = ei + N_EDGES;
    const float* attr   = (const float*)d_in[1];   // [E]
    const int*   target = (const int*)d_in[2];     // [N]
    const float* Wm     = (const float*)d_in[3];   // [C, S]
    float*       out    = (float*)d_out;           // [N, C]

    void* p_deg = nullptr; void* p_cnt = nullptr;
    cudaGetSymbolAddress(&p_deg, g_deg);
    cudaGetSymbolAddress(&p_cnt, g_cnt);
    cudaMemsetAsync(p_deg, 0, N_NODES * sizeof(float));
    cudaMemsetAsync(p_cnt, 0, N_NODES * sizeof(int));

    const int TB = 256;
    int nblk_edges = (N_EDGES + TB - 1) / TB;
    int nblk_warp  = (N_NODES + 7) / 8;    // 8 warps/block, 1 node/warp

    deg_kernel<<<nblk_edges, TB>>>(row, col, attr, target);   // launch 1
    scan_kernel<<<1, SCAN_B>>>();                             // launch 2
    fill_kernel<<<nblk_edges, TB>>>(row, col, attr);          // launch 3

    step1_kernel<<<PERS_BLOCKS, TB>>>(Wm, out);               // launch 4 (s=0)
    for (int s = 1; s < NSTEP; s++) {
        gather_kernel<<<nblk_warp, TB>>>(Wm, out, s);         // launches 5..13
    }
}